// round 13
// baseline (speedup 1.0000x reference)
#include <cuda_runtime.h>
#include <math.h>
#include <stdint.h>
#include <stddef.h>

// Problem constants (fixed by the dataset)
#define NN   2048          // nodes
#define HD   1024          // hidden dim
#define GH   4096          // 4*HD (i,o,u,f)
#define GRID_SCAN 148      // persistent CTAs (<= SM count, 1 CTA/SM)
#define LPC  7             // lanes (hidden units) per CTA: 148*7 = 1036 >= 1024
#define NTH  896           // 28 warps = 7 lanes x 4 gates

// ---------------- device scratch (static allocation only) ----------------
__device__ float g_gx[(size_t)NN * GH];              // 32 MB: gx[n][g*1024+k]
__device__ float g_acc_h [(size_t)(NN + 1) * HD];    // child h sums (slot NN = dummy)
__device__ float g_acc_fc[(size_t)(NN + 1) * HD];    // child f*c sums
__device__ unsigned g_count;                         // barrier arrivals (monotonic)
__device__ volatile unsigned g_phase;                // barrier phase flag

__device__ __forceinline__ float sigmoidf_(float x) { return 1.0f / (1.0f + expf(-x)); }

// ---------------- prologue: zero accumulators + barrier state ----------------
__global__ void zero_kernel() {
    const size_t n4 = (size_t)(NN + 1) * HD / 4;
    const float4 z = make_float4(0.f, 0.f, 0.f, 0.f);
    float4* a = (float4*)g_acc_h;
    float4* b = (float4*)g_acc_fc;
    size_t idx    = (size_t)blockIdx.x * blockDim.x + threadIdx.x;
    size_t stride = (size_t)gridDim.x * blockDim.x;
    for (size_t i = idx; i < n4; i += stride) { a[i] = z; b[i] = z; }
    if (idx == 0) { g_count = 0u; g_phase = 0u; }
}

// ---------------- gx GEMM: gx[n][r] = sum_d Wx[r][d] * emb[inputs[n]][d] + bx[r] ----
#define GBM 128
#define GBN 128
#define GBK 16

__global__ void __launch_bounds__(256) gemm_gx_kernel(
    const int*   __restrict__ inputs,
    const float* __restrict__ emb,
    const float* __restrict__ Wx,     // [4096][1024] row-major (== Wx[4,H,D])
    const float* __restrict__ bx)     // [4096]
{
    __shared__ float As[GBK][GBM];    // X tile, transposed (k-major)
    __shared__ float Bs[GBK][GBN];    // W tile, transposed
    __shared__ int   rowidx[GBM];

    const int bn  = blockIdx.x * GBN;   // output/gate dim (4096)
    const int bm  = blockIdx.y * GBM;   // node dim (2048)
    const int tid = threadIdx.x;
    const int tr  = tid >> 4, tc = tid & 15;   // 16x16 thread grid, 8x8 micro-tile

    if (tid < GBM) rowidx[tid] = inputs[bm + tid];
    __syncthreads();

    float acc[8][8];
    #pragma unroll
    for (int i = 0; i < 8; i++)
        #pragma unroll
        for (int j = 0; j < 8; j++) acc[i][j] = 0.f;

    for (int k0 = 0; k0 < HD; k0 += GBK) {
        #pragma unroll
        for (int i = 0; i < 2; i++) {
            int slot = tid + i * 256;         // 0..511
            int row  = slot >> 2;             // 0..127
            int c4   = (slot & 3) << 2;       // 0,4,8,12
            float4 va = *(const float4*)(emb + (size_t)rowidx[row] * HD + k0 + c4);
            As[c4 + 0][row] = va.x; As[c4 + 1][row] = va.y;
            As[c4 + 2][row] = va.z; As[c4 + 3][row] = va.w;
            float4 vb = *(const float4*)(Wx + (size_t)(bn + row) * HD + k0 + c4);
            Bs[c4 + 0][row] = vb.x; Bs[c4 + 1][row] = vb.y;
            Bs[c4 + 2][row] = vb.z; Bs[c4 + 3][row] = vb.w;
        }
        __syncthreads();
        #pragma unroll
        for (int kk = 0; kk < GBK; kk++) {
            float a[8], b[8];
            *(float4*)&a[0] = *(const float4*)&As[kk][tr * 8];
            *(float4*)&a[4] = *(const float4*)&As[kk][tr * 8 + 4];
            *(float4*)&b[0] = *(const float4*)&Bs[kk][tc * 8];
            *(float4*)&b[4] = *(const float4*)&Bs[kk][tc * 8 + 4];
            #pragma unroll
            for (int i = 0; i < 8; i++)
                #pragma unroll
                for (int j = 0; j < 8; j++)
                    acc[i][j] += a[i] * b[j];
        }
        __syncthreads();
    }

    #pragma unroll
    for (int i = 0; i < 8; i++) {
        int r = bm + tr * 8 + i;
        float* dst = g_gx + (size_t)r * GH + bn + tc * 8;
        #pragma unroll
        for (int j = 0; j < 8; j++)
            dst[j] = acc[i][j] + bx[bn + tc * 8 + j];
    }
}

// ---------------- persistent sequential scan ----------------
// Step t (one grid barrier per step):
//   combined 4096x1024 matvec: gates i/o/u use v = acc_h[t] (+ h_{t-1} if parent[t-1]==t),
//                               gate f row uses h_{t-1}  (deferred forget gate of node t-1)
//   finalize (per owned lane k, all elementwise-local):
//     f_{t-1} = sig(gx[p,3,k] + Wh3.h_{t-1} + bh3), p = parent[t-1]
//     if p != t: acc_h[p][k] += h_{t-1}[k]; acc_fc[p][k] += f*c_{t-1}[k]   (else forward locally)
//     i,o,u from gx[t] + dots + bh; c_t = i*u + acc_fc[t][k] (+fwd); h_t = o*tanh(c_t)
__global__ void __launch_bounds__(NTH, 1) scan_kernel(
    const int*   __restrict__ parent,
    const float* __restrict__ Wh,     // [4][1024][1024]
    const float* __restrict__ bh,     // [4][1024]
    float*       out, int out_size)
{
    __shared__ float sv[HD];      // hsum_t input vector
    __shared__ float shv[HD];     // h_{t-1} input vector
    __shared__ float sdot[32];    // per-row dot results (28 used)

    const int tid = threadIdx.x;
    const int cta = blockIdx.x;
    const int w = tid >> 5, e = tid & 31;
    const int l = w >> 2, g = w & 3;          // warp w -> lane l, gate g
    const int k = cta * LPC + l;              // global hidden-unit index of this warp
    const bool active = (k < HD);

    // --- load this warp's weight row into registers (32 floats/thread) ---
    float4 wreg[8];
    if (active) {
        const float4* src = (const float4*)(Wh + ((size_t)g * HD + k) * HD);
        #pragma unroll
        for (int i = 0; i < 8; i++) wreg[i] = src[e + i * 32];
    } else {
        #pragma unroll
        for (int i = 0; i < 8; i++) wreg[i] = make_float4(0.f, 0.f, 0.f, 0.f);
    }

    // finalize-thread persistent state (threads 0..6 own one lane each)
    const int kf = cta * LPC + tid;
    const bool fin = (tid < LPC) && (kf < HD);
    float bh0 = 0.f, bh1 = 0.f, bh2 = 0.f, bh3v = 0.f;
    if (fin) {
        bh0 = bh[kf]; bh1 = bh[HD + kf]; bh2 = bh[2 * HD + kf]; bh3v = bh[3 * HD + kf];
    }
    float c_prev = 0.f;
    const float* gxc = (const float*)g_gx;

    for (int t = 0; t < NN; t++) {
        const int pprev = (t > 0) ? __ldg(parent + (t - 1)) : -1;

        // prefetch finalize-phase scalars early (independent of the dots)
        float pre_gi = 0.f, pre_go = 0.f, pre_gu = 0.f, pre_gf = 0.f, pre_accfc = 0.f;
        if (fin) {
            const float* gxr = gxc + (size_t)t * GH + kf;
            pre_gi = __ldg(gxr);
            pre_go = __ldg(gxr + HD);
            pre_gu = __ldg(gxr + 2 * HD);
            pre_accfc = __ldcg(g_acc_fc + (size_t)t * HD + kf);
            if (t > 0) pre_gf = __ldg(gxc + (size_t)pprev * GH + 3 * HD + kf);
        }

        // phase 1: stage input vectors in SMEM
        for (int kk = tid; kk < HD; kk += NTH) {
            float hp = (t > 0) ? __ldcg(out + (size_t)(t - 1) * HD + kk) : 0.f;
            shv[kk] = hp;
            float v = __ldcg(g_acc_h + (size_t)t * HD + kk);
            if (pprev == t) v += hp;              // forward h_{t-1} into hsum_t locally
            sv[kk] = v;
        }
        __syncthreads();

        // phase 2: 28 warp dot-products (weights in registers, vec from SMEM)
        if (active) {
            const float4* vec4 = (const float4*)((g < 3) ? sv : shv);
            float s0 = 0.f, s1 = 0.f, s2 = 0.f, s3 = 0.f;
            #pragma unroll
            for (int i = 0; i < 8; i++) {
                float4 b = vec4[e + i * 32];
                s0 += wreg[i].x * b.x;
                s1 += wreg[i].y * b.y;
                s2 += wreg[i].z * b.z;
                s3 += wreg[i].w * b.w;
            }
            float s = (s0 + s1) + (s2 + s3);
            #pragma unroll
            for (int off = 16; off; off >>= 1)
                s += __shfl_down_sync(0xffffffffu, s, off);
            if (e == 0) sdot[w] = s;
        }
        __syncthreads();

        // phase 3: finalize (one thread per owned lane)
        if (fin) {
            float yi = sdot[tid * 4 + 0];
            float yo = sdot[tid * 4 + 1];
            float yu = sdot[tid * 4 + 2];
            float zf = sdot[tid * 4 + 3];

            float fc_fwd = 0.f;
            if (t > 0) {
                float f  = sigmoidf_(pre_gf + zf + bh3v);     // forget gate of node t-1
                float fc = f * c_prev;
                float hp = shv[kf];
                if (pprev == t) {
                    fc_fwd = fc;                              // forward locally, no mem write
                } else {
                    size_t a = (size_t)pprev * HD + kf;
                    g_acc_h [a] = __ldcg(g_acc_h  + a) + hp;
                    g_acc_fc[a] = __ldcg(g_acc_fc + a) + fc;
                }
            }
            float iv = sigmoidf_(pre_gi + yi + bh0);
            float ov = sigmoidf_(pre_go + yo + bh1);
            float uv = tanhf    (pre_gu + yu + bh2);
            float c  = iv * uv + pre_accfc + fc_fwd;
            float h  = ov * tanhf(c);

            out[(size_t)t * HD + kf] = h;
            c_prev = c;
            if (t == NN - 1 && out_size >= NN * HD + 2 * HD) {
                out[(size_t)NN * HD + kf]      = c;   // root c
                out[(size_t)NN * HD + HD + kf] = h;   // root h
            }
        }
        __syncthreads();

        // grid barrier (monotonic counter + phase flag)
        if (tid == 0) {
            __threadfence();                               // release: stores -> L2
            unsigned old = atomicAdd(&g_count, 1u);
            unsigned tgt = (unsigned)(t + 1) * (unsigned)GRID_SCAN;
            if (old == tgt - 1u) {
                g_phase = (unsigned)(t + 1);
            } else {
                while (g_phase < (unsigned)(t + 1)) { }
                __threadfence();                           // acquire: drop stale L1
            }
        }
        __syncthreads();
    }
}

// ---------------- launch ----------------
extern "C" void kernel_launch(void* const* d_in, const int* in_sizes, int n_in,
                              void* d_out, int out_size) {
    const int*   inputs = (const int*)  d_in[0];
    const int*   parent = (const int*)  d_in[1];
    const float* emb    = (const float*)d_in[2];
    const float* Wx     = (const float*)d_in[3];
    const float* bx     = (const float*)d_in[4];
    const float* Wh     = (const float*)d_in[5];
    const float* bh     = (const float*)d_in[6];
    float* out = (float*)d_out;

    zero_kernel<<<256, 256>>>();

    dim3 gg(GH / GBN, NN / GBM);   // (32, 16)
    gemm_gx_kernel<<<gg, 256>>>(inputs, emb, Wx, bx);

    scan_kernel<<<GRID_SCAN, NTH>>>(parent, Wh, bh, out, out_size);
}

// round 17
// speedup vs baseline: 1.3317x; 1.3317x over previous
#include <cuda_runtime.h>
#include <math.h>
#include <stdint.h>
#include <stddef.h>

// Problem constants (fixed by the dataset)
#define NN   2048          // nodes
#define HD   1024          // hidden dim
#define GH   4096          // 4*HD (i,o,u,f)
#define GRID_SCAN 148      // persistent CTAs (1 CTA/SM)
#define LPC  7             // lanes (hidden units) per CTA: 148*7 = 1036 >= 1024
#define NTH  896           // 28 warps = 7 lanes x 4 gates

// ---------------- device scratch (static allocation only) ----------------
__device__ float g_gx[(size_t)NN * GH];        // 32 MB: gx[n][g*1024+k]
__device__ unsigned g_count;                   // barrier arrivals (monotonic)
__device__ volatile unsigned g_phase;          // barrier phase flag

__device__ __forceinline__ float sig_(float x) {
    return __fdividef(1.0f, 1.0f + __expf(-x));
}
__device__ __forceinline__ float tanh_(float x) {
    float ax = fabsf(x);
    float ex = __expf(2.0f * ax);                 // saturates to +inf safely
    float r  = 1.0f - __fdividef(2.0f, ex + 1.0f);
    return copysignf(r, x);
}

// ---------------- prologue: reset barrier state ----------------
__global__ void init_kernel() {
    if (threadIdx.x == 0) { g_count = 0u; g_phase = 0u; }
}

// ---------------- gx GEMM: gx[n][r] = sum_d Wx[r][d] * emb[inputs[n]][d] + bx[r] ----
#define GBM 128
#define GBN 128
#define GBK 16

__global__ void __launch_bounds__(256) gemm_gx_kernel(
    const int*   __restrict__ inputs,
    const float* __restrict__ emb,
    const float* __restrict__ Wx,     // [4096][1024] row-major (== Wx[4,H,D])
    const float* __restrict__ bx)     // [4096]
{
    __shared__ float As[GBK][GBM];    // X tile, transposed (k-major)
    __shared__ float Bs[GBK][GBN];    // W tile, transposed
    __shared__ int   rowidx[GBM];

    const int bn  = blockIdx.x * GBN;   // output/gate dim (4096)
    const int bm  = blockIdx.y * GBM;   // node dim (2048)
    const int tid = threadIdx.x;
    const int tr  = tid >> 4, tc = tid & 15;   // 16x16 thread grid, 8x8 micro-tile

    if (tid < GBM) rowidx[tid] = inputs[bm + tid];
    __syncthreads();

    float acc[8][8];
    #pragma unroll
    for (int i = 0; i < 8; i++)
        #pragma unroll
        for (int j = 0; j < 8; j++) acc[i][j] = 0.f;

    for (int k0 = 0; k0 < HD; k0 += GBK) {
        #pragma unroll
        for (int i = 0; i < 2; i++) {
            int slot = tid + i * 256;         // 0..511
            int row  = slot >> 2;             // 0..127
            int c4   = (slot & 3) << 2;       // 0,4,8,12
            float4 va = *(const float4*)(emb + (size_t)rowidx[row] * HD + k0 + c4);
            As[c4 + 0][row] = va.x; As[c4 + 1][row] = va.y;
            As[c4 + 2][row] = va.z; As[c4 + 3][row] = va.w;
            float4 vb = *(const float4*)(Wx + (size_t)(bn + row) * HD + k0 + c4);
            Bs[c4 + 0][row] = vb.x; Bs[c4 + 1][row] = vb.y;
            Bs[c4 + 2][row] = vb.z; Bs[c4 + 3][row] = vb.w;
        }
        __syncthreads();
        #pragma unroll
        for (int kk = 0; kk < GBK; kk++) {
            float a[8], b[8];
            *(float4*)&a[0] = *(const float4*)&As[kk][tr * 8];
            *(float4*)&a[4] = *(const float4*)&As[kk][tr * 8 + 4];
            *(float4*)&b[0] = *(const float4*)&Bs[kk][tc * 8];
            *(float4*)&b[4] = *(const float4*)&Bs[kk][tc * 8 + 4];
            #pragma unroll
            for (int i = 0; i < 8; i++)
                #pragma unroll
                for (int j = 0; j < 8; j++)
                    acc[i][j] += a[i] * b[j];
        }
        __syncthreads();
    }

    #pragma unroll
    for (int i = 0; i < 8; i++) {
        int r = bm + tr * 8 + i;
        float* dst = g_gx + (size_t)r * GH + bn + tc * 8;
        #pragma unroll
        for (int j = 0; j < 8; j++)
            dst[j] = acc[i][j] + bx[bn + tc * 8 + j];
    }
}

// ---------------- persistent sequential scan ----------------
// Exploits parent[t] in [t+1, t+8]: child-sum accumulator is an 8-slot SMEM
// ring replicated per CTA, fed by the h_{t-1} broadcast each CTA reads anyway;
// the f*c accumulator is a lane-owned 8-slot SMEM ring. Per-step global
// traffic: read h_{t-1} (4KB) + gx scalars; write 7 h lanes; proven
// counter+phase grid barrier (R13).
__global__ void __launch_bounds__(NTH, 1) scan_kernel(
    const int*   __restrict__ parent,
    const float* __restrict__ Wh,     // [4][1024][1024]
    const float* __restrict__ bh,     // [4][1024]
    float*       out, int out_size)
{
    __shared__ float sacc[8][HD];     // child h-sum ring (full width, replicated)
    __shared__ float shv[HD];         // h_{t-1}
    __shared__ float sdot[32];        // per-warp dot results (28 used)
    __shared__ float sfc[8][LPC];     // child f*c ring (owned lanes only)
    __shared__ int   spar[NN];        // parent[] cached in SMEM

    const int tid = threadIdx.x;
    const int cta = blockIdx.x;
    const int w = tid >> 5, e = tid & 31;
    const int l = w >> 2, g = w & 3;          // warp w -> lane l, gate g
    const int k = cta * LPC + l;              // hidden-unit index of this warp
    const bool active = (k < HD);

    // prologue: zero rings, cache parent
    {
        float4* sa4 = (float4*)sacc;
        const float4 z4 = make_float4(0.f, 0.f, 0.f, 0.f);
        for (int i = tid; i < 8 * HD / 4; i += NTH) sa4[i] = z4;
        if (tid < 8 * LPC) ((float*)sfc)[tid] = 0.f;
        for (int i = tid; i < NN; i += NTH) spar[i] = parent[i];
    }

    // this warp's Wh row in registers (32 floats/thread)
    float4 wreg[8];
    if (active) {
        const float4* src = (const float4*)(Wh + ((size_t)g * HD + k) * HD);
        #pragma unroll
        for (int i = 0; i < 8; i++) wreg[i] = src[e + i * 32];
    } else {
        #pragma unroll
        for (int i = 0; i < 8; i++) wreg[i] = make_float4(0.f, 0.f, 0.f, 0.f);
    }

    // finalize threads: tid 0..6 own one lane each (all in warp 0)
    const int kf = cta * LPC + tid;
    const bool fin = (tid < LPC) && (kf < HD);
    float bh0 = 0.f, bh1 = 0.f, bh2 = 0.f, bh3v = 0.f;
    if (fin) {
        bh0 = bh[kf]; bh1 = bh[HD + kf]; bh2 = bh[2 * HD + kf]; bh3v = bh[3 * HD + kf];
    }
    float c_prev = 0.f;
    __syncthreads();

    for (int t = 0; t < NN; t++) {
        const int pprev  = (t > 0) ? spar[t - 1] : 0;
        const int slot_p = pprev & 7;
        const int slot_t = t & 7;

        // prefetch gx scalars (read-only, independent -> overlaps everything)
        float pre_gi = 0.f, pre_go = 0.f, pre_gu = 0.f, pre_gf = 0.f;
        if (fin) {
            const float* gxr = g_gx + (size_t)t * GH + kf;
            pre_gi = __ldg(gxr);
            pre_go = __ldg(gxr + HD);
            pre_gu = __ldg(gxr + 2 * HD);
            if (t > 0) pre_gf = __ldg(g_gx + (size_t)pprev * GH + 3 * HD + kf);
        }

        // phase 1: stage h_{t-1} (vectorized, 256 threads x float4) and fold it
        // into the child-sum ring slot of its parent
        if (tid < HD / 4) {
            float4* sh4 = (float4*)shv;
            if (t > 0) {
                float4 hp = __ldcg((const float4*)(out + (size_t)(t - 1) * HD) + tid);
                sh4[tid] = hp;
                float4* sa4 = (float4*)sacc[slot_p];
                float4 a = sa4[tid];
                a.x += hp.x; a.y += hp.y; a.z += hp.z; a.w += hp.w;
                sa4[tid] = a;                 // each element touched by one thread
            } else {
                sh4[tid] = make_float4(0.f, 0.f, 0.f, 0.f);
            }
        }
        __syncthreads();

        // phase 2: 28 warp dots: i/o/u rows on hsum_t = sacc[slot_t], f on h_{t-1}
        if (active) {
            const float4* vec4 = (const float4*)((g < 3) ? sacc[slot_t] : shv);
            float s0 = 0.f, s1 = 0.f, s2 = 0.f, s3 = 0.f;
            #pragma unroll
            for (int i = 0; i < 8; i++) {
                float4 b = vec4[e + i * 32];
                s0 += wreg[i].x * b.x;
                s1 += wreg[i].y * b.y;
                s2 += wreg[i].z * b.z;
                s3 += wreg[i].w * b.w;
            }
            float s = (s0 + s1) + (s2 + s3);
            #pragma unroll
            for (int off = 16; off; off >>= 1)
                s += __shfl_down_sync(0xffffffffu, s, off);
            if (e == 0) sdot[w] = s;
        }
        __syncthreads();

        // recycle child-sum slot t for node t+8 (next write is after next barrier)
        if (tid < HD / 4)
            ((float4*)sacc[slot_t])[tid] = make_float4(0.f, 0.f, 0.f, 0.f);

        // phase 3: finalize owned lanes
        if (fin) {
            float yi = sdot[tid * 4 + 0];
            float yo = sdot[tid * 4 + 1];
            float yu = sdot[tid * 4 + 2];
            float zf = sdot[tid * 4 + 3];

            if (t > 0) {   // deferred forget gate of node t-1 -> parent's fc ring
                float f = sig_(pre_gf + zf + bh3v);
                sfc[slot_p][tid] += f * c_prev;
            }
            float accfc = sfc[slot_t][tid];   // includes fc if pprev == t
            sfc[slot_t][tid] = 0.f;           // recycle (same thread owns it)

            float iv = sig_(pre_gi + yi + bh0);
            float ov = sig_(pre_go + yo + bh1);
            float uv = tanh_(pre_gu + yu + bh2);
            float c  = iv * uv + accfc;
            float h  = ov * tanh_(c);
            c_prev = c;

            __stcg(out + (size_t)t * HD + kf, h);
            if (t == NN - 1 && out_size >= NN * HD + 2 * HD) {
                __stcg(out + (size_t)NN * HD + kf,      c);   // root c
                __stcg(out + (size_t)NN * HD + HD + kf, h);   // root h
            }
            __threadfence();   // each h-writer releases its own stores to L2
        }
        __syncthreads();

        // grid barrier (proven R13 construction: monotonic counter + phase flag)
        if (tid == 0) {
            __threadfence();
            unsigned old = atomicAdd(&g_count, 1u);
            unsigned tgt = (unsigned)(t + 1) * (unsigned)GRID_SCAN;
            if (old == tgt - 1u) {
                g_phase = (unsigned)(t + 1);
            } else {
                while (g_phase < (unsigned)(t + 1)) { }
                __threadfence();
            }
        }
        __syncthreads();
    }
}

// ---------------- launch ----------------
extern "C" void kernel_launch(void* const* d_in, const int* in_sizes, int n_in,
                              void* d_out, int out_size) {
    const int*   inputs = (const int*)  d_in[0];
    const int*   parent = (const int*)  d_in[1];
    const float* emb    = (const float*)d_in[2];
    const float* Wx     = (const float*)d_in[3];
    const float* bx     = (const float*)d_in[4];
    const float* Wh     = (const float*)d_in[5];
    const float* bh     = (const float*)d_in[6];
    float* out = (float*)d_out;

    init_kernel<<<1, 32>>>();

    dim3 gg(GH / GBN, NN / GBM);   // (32, 16)
    gemm_gx_kernel<<<gg, 256>>>(inputs, emb, Wx, bx);

    scan_kernel<<<GRID_SCAN, NTH>>>(parent, Wh, bh, out, out_size);
}